// round 13
// baseline (speedup 1.0000x reference)
#include <cuda_runtime.h>
#include <cuda_fp16.h>
#include <cstdint>

#define BB 32
#define LL 4096
#define EE 512
#define HH 512
#define AA 256

// ---------------- scratch (__device__ globals; no allocs allowed) ----------
__device__ float g_dec[BB * AA];                 // dec_attn + b_enc + b_dec
__device__ float g_scores[BB * LL];              // pre-softmax scores
__device__ float g_bm[BB * 32];                  // per-score-block max
__device__ float g_bs[BB * 32];                  // per-score-block sum-exp
__device__ float g_partial[BB * 64 * EE];        // weighted-sum partials
__device__ __half g_Bh[AA * EE];                 // W_enc^T fp16, [a][k] K-major
__device__ __half g_feat16[(size_t)BB * LL * EE]; // fp16 features (score writes)

// ---------------- family-portable PTX helpers ------------------------------
__device__ __forceinline__ uint32_t smem_u32(const void* p) {
    uint32_t a;
    asm("{ .reg .u64 t; cvta.to.shared.u64 t, %1; cvt.u32.u64 %0, t; }"
        : "=r"(a) : "l"(p));
    return a;
}
__device__ __forceinline__ uint32_t pack_h2(float lo, float hi) {
    uint32_t r;
    asm("cvt.rn.f16x2.f32 %0, %1, %2;" : "=r"(r) : "f"(hi), "f"(lo));
    return r;
}
#define LDSM4(r, addr)                                                        \
    asm volatile("ldmatrix.sync.aligned.m8n8.x4.shared.b16 {%0,%1,%2,%3}, [%4];" \
        : "=r"((r)[0]), "=r"((r)[1]), "=r"((r)[2]), "=r"((r)[3]) : "r"(addr))

#define MMA_F16(d, a, b0, b1)                                                 \
    asm volatile("mma.sync.aligned.m16n8k16.row.col.f32.f16.f16.f32 "         \
        "{%0,%1,%2,%3}, {%4,%5,%6,%7}, {%8,%9}, {%0,%1,%2,%3};"               \
        : "+f"((d)[0]), "+f"((d)[1]), "+f"((d)[2]), "+f"((d)[3])              \
        : "r"((a)[0]), "r"((a)[1]), "r"((a)[2]), "r"((a)[3]),                 \
          "r"(b0), "r"(b1))

#define CP16(dst, src)                                                        \
    asm volatile("cp.async.cg.shared.global [%0], [%1], 16;"                  \
        :: "r"(dst), "l"(src) : "memory")
#define CP_COMMIT() asm volatile("cp.async.commit_group;" ::: "memory")
#define CP_WAIT0()  asm volatile("cp.async.wait_group 0;" ::: "memory")
#define CP_WAIT1()  asm volatile("cp.async.wait_group 1;" ::: "memory")

// ---------------- SMEM layout for score kernel (bytes) ---------------------
#define SA 72                // padded k-stride (halfs) -> conflict-free ldmatrix
#define OFF_DEC 0            // 256 f32
#define OFF_WV  1024         // 256 f32
#define OFF_RED 2048         // reduce + stats scratch
#define OFF_A   4096         // A ring: 3 x (128 x SA halfs)
#define A_STRIDE 18432
#define OFF_B   59392        // B ring: 3 x (256 x SA halfs)
#define B_STRIDE 36864
#define SMEM_BYTES 169984

// ---------------------------------------------------------------------------
// setup: blocks [0,32) tiled transpose W_enc -> fp16 K-major (coalesced);
//        blocks [32,64) dec projection.
// ---------------------------------------------------------------------------
__global__ __launch_bounds__(256) void setup_kernel(
    const float* __restrict__ W_enc, const float* __restrict__ dh,
    const float* __restrict__ W_dec, const float* __restrict__ b_enc,
    const float* __restrict__ b_dec)
{
    if (blockIdx.x < 32) {
        __shared__ __half sh[64][65];
        const int kt = blockIdx.x >> 2;
        const int at = blockIdx.x & 3;
        const int k0 = kt * 64, a0 = at * 64;
#pragma unroll
        for (int i = 0; i < 16; i++) {
            int idx = threadIdx.x + i * 256;
            int r = idx >> 6, ca = idx & 63;
            sh[ca][r] = __float2half_rn(W_enc[(size_t)(k0 + r) * AA + a0 + ca]);
        }
        __syncthreads();
#pragma unroll
        for (int i = 0; i < 16; i++) {
            int idx = threadIdx.x + i * 256;
            int arr = idx >> 6, ck = idx & 63;
            g_Bh[(size_t)(a0 + arr) * EE + k0 + ck] = sh[arr][ck];
        }
    } else {
        int b = blockIdx.x - 32, a = threadIdx.x;
        __shared__ float shh[HH];
        for (int h = threadIdx.x; h < HH; h += 256) shh[h] = dh[b * HH + h];
        __syncthreads();
        float acc = 0.f;
#pragma unroll 8
        for (int h = 0; h < HH; h++) acc = fmaf(shh[h], W_dec[h * AA + a], acc);
        g_dec[b * AA + a] = acc + b_enc[a] + b_dec[a];
    }
}

// ---------------------------------------------------------------------------
// Fused score GEMM (single-term fp16, f32 accum), triple-buffered rings.
// Also streams the fp16 feature conversion to g_feat16 for the wsum pass.
// ---------------------------------------------------------------------------
__global__ __launch_bounds__(512, 1) void score_kernel(
    const float* __restrict__ features,
    const float* __restrict__ W_v,
    const float* __restrict__ b_v)
{
    extern __shared__ __align__(16) char smem[];
    const uint32_t sb = smem_u32(smem);

    const int tid  = threadIdx.x;
    const int lane = tid & 31;
    const int wid  = tid >> 5;
    const int warp_m = wid & 3;
    const int warp_n = wid >> 2;
    const int row0 = blockIdx.x * 128;
    const int b    = row0 >> 12;

    float* sdec = (float*)(smem + OFF_DEC);
    float* swv  = (float*)(smem + OFF_WV);
    float* sred = (float*)(smem + OFF_RED);
    if (tid < 256) {
        sdec[tid] = g_dec[b * AA + tid];
        swv[tid]  = W_v[tid];
    }

    const int m_base = warp_m * 32;
    const int n_base = warp_n * 64;
    const uint32_t aoff =
        (uint32_t)((m_base + (lane & 15)) * SA + (lane >> 4) * 8) * 2;
    const uint32_t boff =
        (uint32_t)((n_base + (lane >> 4) * 8 + (lane & 7)) * SA +
                   ((lane >> 3) & 1) * 8) * 2;

    float d[2][8][4];
#pragma unroll
    for (int mt = 0; mt < 2; mt++)
#pragma unroll
        for (int nt = 0; nt < 8; nt++)
#pragma unroll
            for (int q = 0; q < 4; q++) d[mt][nt][q] = 0.f;

    // A loads: thread covers row tid/4, 16 floats at col (tid&3)*16
    const int ar = tid >> 2, aq = tid & 3;
    const float4* f4 = (const float4*)features +
                       ((size_t)row0 + ar) * 128 + aq * 4;
    const uint32_t a_sts = (uint32_t)(ar * SA + aq * 16) * 2;
    __half* gf = g_feat16 + ((size_t)row0 + ar) * EE + aq * 16;

    float4 fr[4];

    auto cp_b = [&](int chunk) {
        const uint32_t base = sb + OFF_B + (uint32_t)(chunk % 3) * B_STRIDE;
        const int k0 = chunk * 64;
#pragma unroll
        for (int i = 0; i < 4; i++) {
            int idx = tid + i * 512;            // [0,2048)
            int a = idx >> 3, seg = idx & 7;
            uint32_t dst = base + (uint32_t)(a * SA + seg * 8) * 2;
            CP16(dst, g_Bh + (size_t)a * EE + k0 + seg * 8);
        }
        CP_COMMIT();
    };
    auto lda = [&](int chunk) {
#pragma unroll
        for (int j = 0; j < 4; j++) fr[j] = f4[chunk * 16 + j];
    };
    auto sts_a = [&](int chunk) {
        uint4 u0 = make_uint4(
            pack_h2(fr[0].x, fr[0].y), pack_h2(fr[0].z, fr[0].w),
            pack_h2(fr[1].x, fr[1].y), pack_h2(fr[1].z, fr[1].w));
        uint4 u1 = make_uint4(
            pack_h2(fr[2].x, fr[2].y), pack_h2(fr[2].z, fr[2].w),
            pack_h2(fr[3].x, fr[3].y), pack_h2(fr[3].z, fr[3].w));
        char* dst = smem + OFF_A + (chunk % 3) * A_STRIDE + a_sts;
        *(uint4*)dst = u0;
        *(uint4*)(dst + 16) = u1;
        // stream fp16 copy for wsum pass (fire-and-forget)
        __half* g = gf + chunk * 64;
        *(uint4*)g = u0;
        *(uint4*)(g + 8) = u1;
    };

    // prologue: B(0),B(1) in flight; A(0) staged; A(1) in regs
    cp_b(0);
    cp_b(1);
    lda(0); sts_a(0);
    lda(1);

    for (int c = 0; c < 8; c++) {
        if (c < 7) sts_a(c + 1);           // A ring slot (c+1)%3 — disjoint
        if (c < 7) CP_WAIT1(); else CP_WAIT0();   // B(c) complete
        __syncthreads();                   // A(c)+B(c) visible; prev compute done
        if (c < 6) {
            cp_b(c + 2);                   // B slot (c+2)%3 — readers past bar
            lda(c + 2);
        }

        const uint32_t aBase = sb + OFF_A + (uint32_t)(c % 3) * A_STRIDE + aoff;
        const uint32_t bBase = sb + OFF_B + (uint32_t)(c % 3) * B_STRIDE;
#pragma unroll
        for (int ks = 0; ks < 4; ks++) {
            uint32_t ah[2][4];
#pragma unroll
            for (int mt = 0; mt < 2; mt++)
                LDSM4(ah[mt], aBase + (uint32_t)(mt * 16 * SA + ks * 16) * 2);
#pragma unroll
            for (int ntp = 0; ntp < 4; ntp++) {
                uint32_t bh[4];
                LDSM4(bh, bBase + boff +
                          (uint32_t)(ntp * 16 * SA + ks * 16) * 2);
#pragma unroll
                for (int mt = 0; mt < 2; mt++)
#pragma unroll
                    for (int t = 0; t < 2; t++)
                        MMA_F16(d[mt][ntp * 2 + t], ah[mt],
                                bh[2 * t], bh[2 * t + 1]);
            }
        }
    }

    // ---- epilogue: + dec, relu, dot W_v; quad shuffle + 4-way smem reduce --
    __syncthreads();
#pragma unroll
    for (int mt = 0; mt < 2; mt++) {
        float s0 = 0.f, s1 = 0.f;
#pragma unroll
        for (int nt = 0; nt < 8; nt++) {
            int c0 = n_base + nt * 8 + (lane & 3) * 2;
            float e0 = sdec[c0], e1 = sdec[c0 + 1];
            float w0 = swv[c0], w1 = swv[c0 + 1];
            s0 = fmaf(fmaxf(d[mt][nt][0] + e0, 0.f), w0, s0);
            s0 = fmaf(fmaxf(d[mt][nt][1] + e1, 0.f), w1, s0);
            s1 = fmaf(fmaxf(d[mt][nt][2] + e0, 0.f), w0, s1);
            s1 = fmaf(fmaxf(d[mt][nt][3] + e1, 0.f), w1, s1);
        }
        s0 += __shfl_xor_sync(~0u, s0, 1);
        s0 += __shfl_xor_sync(~0u, s0, 2);
        s1 += __shfl_xor_sync(~0u, s1, 1);
        s1 += __shfl_xor_sync(~0u, s1, 2);
        if ((lane & 3) == 0) {
            int r = m_base + mt * 16 + (lane >> 2);
            sred[r * 4 + warp_n] = s0;
            sred[(r + 8) * 4 + warp_n] = s1;
        }
    }
    __syncthreads();

    float s = -1e30f;
    if (tid < 128) {
        s = sred[tid * 4] + sred[tid * 4 + 1] +
            sred[tid * 4 + 2] + sred[tid * 4 + 3] + b_v[0];
        g_scores[row0 + tid] = s;
    }
    __syncthreads();

    // ---- per-block softmax stats --------------------------------------------
    float* st = sred;
    float m = s;
#pragma unroll
    for (int o = 16; o; o >>= 1) m = fmaxf(m, __shfl_xor_sync(~0u, m, o));
    if (lane == 0) st[wid] = m;
    __syncthreads();
    if (tid == 0) {
        float M = st[0];
#pragma unroll
        for (int i = 1; i < 16; i++) M = fmaxf(M, st[i]);
        st[16] = M;
    }
    __syncthreads();
    const float M = st[16];
    float e = (tid < 128) ? __expf(s - M) : 0.f;
#pragma unroll
    for (int o = 16; o; o >>= 1) e += __shfl_xor_sync(~0u, e, o);
    __syncthreads();
    if (lane == 0) st[wid] = e;
    __syncthreads();
    if (tid == 0) {
        float S = 0.f;
#pragma unroll
        for (int i = 0; i < 16; i++) S += st[i];
        g_bm[blockIdx.x] = M;
        g_bs[blockIdx.x] = S;
    }
}

// ---------------------------------------------------------------------------
// wsum_attn: exact softmax weights -> attn; partial weighted sums reading the
// fp16 feature copy (half traffic). 64 chunks x 64 L-rows; half2 lanes.
// ---------------------------------------------------------------------------
__global__ __launch_bounds__(512) void wsum_attn(float* __restrict__ attn)
{
    const int b = blockIdx.y, chunk = blockIdx.x;
    const int tid = threadIdx.x;
    __shared__ float sw[64];
    __shared__ float MS[2];
    __shared__ float2 ps2[512];           // [rowgrp][256 half2-cols]

    if (tid < 32) {
        float m = g_bm[b * 32 + tid];
        float sloc = g_bs[b * 32 + tid];
        float M = m;
#pragma unroll
        for (int o = 16; o; o >>= 1) M = fmaxf(M, __shfl_xor_sync(~0u, M, o));
        float S = sloc * __expf(m - M);
#pragma unroll
        for (int o = 16; o; o >>= 1) S += __shfl_xor_sync(~0u, S, o);
        if (tid == 0) { MS[0] = M; MS[1] = S; }
    }
    __syncthreads();
    if (tid < 64) {
        int l = chunk * 64 + tid;
        float w = __expf(g_scores[(size_t)b * LL + l] - MS[0]) / MS[1];
        sw[tid] = w;
        attn[(size_t)b * LL + l] = w;
    }
    __syncthreads();

    const int e2 = tid & 255;              // half2 column
    const int rg = tid >> 8;               // row group 0/1 (32 rows each)
    const __half* fp = g_feat16 +
        ((size_t)b * LL + (size_t)chunk * 64 + rg * 32) * EE + e2 * 2;

    float ax0 = 0.f, ay0 = 0.f, ax1 = 0.f, ay1 = 0.f;
    float ax2 = 0.f, ay2 = 0.f, ax3 = 0.f, ay3 = 0.f;
#pragma unroll
    for (int i = 0; i < 32; i += 4) {
        float2 v0 = __half22float2(*(const __half2*)(fp + (size_t)(i + 0) * EE));
        float2 v1 = __half22float2(*(const __half2*)(fp + (size_t)(i + 1) * EE));
        float2 v2 = __half22float2(*(const __half2*)(fp + (size_t)(i + 2) * EE));
        float2 v3 = __half22float2(*(const __half2*)(fp + (size_t)(i + 3) * EE));
        float w0 = sw[rg * 32 + i + 0];
        float w1 = sw[rg * 32 + i + 1];
        float w2 = sw[rg * 32 + i + 2];
        float w3 = sw[rg * 32 + i + 3];
        ax0 = fmaf(v0.x, w0, ax0); ay0 = fmaf(v0.y, w0, ay0);
        ax1 = fmaf(v1.x, w1, ax1); ay1 = fmaf(v1.y, w1, ay1);
        ax2 = fmaf(v2.x, w2, ax2); ay2 = fmaf(v2.y, w2, ay2);
        ax3 = fmaf(v3.x, w3, ax3); ay3 = fmaf(v3.y, w3, ay3);
    }
    ps2[rg * 256 + e2] = make_float2((ax0 + ax1) + (ax2 + ax3),
                                     (ay0 + ay1) + (ay2 + ay3));
    __syncthreads();

    const float* psf = (const float*)ps2;
    g_partial[((size_t)b * 64 + chunk) * EE + tid] = psf[tid] + psf[512 + tid];
}

// ---------------------------------------------------------------------------
// wsum_reduce: float4 per thread over 64 partials
// ---------------------------------------------------------------------------
__global__ __launch_bounds__(128) void wsum_reduce(float* __restrict__ out)
{
    int idx4 = blockIdx.x * 128 + threadIdx.x;   // [0, B*E/4)
    int b = idx4 >> 7, q = idx4 & 127;
    const float4* p = (const float4*)g_partial + (size_t)b * 64 * 128 + q;
    float4 a0 = make_float4(0.f, 0.f, 0.f, 0.f);
    float4 a1 = make_float4(0.f, 0.f, 0.f, 0.f);
#pragma unroll
    for (int c = 0; c < 64; c += 2) {
        float4 v0 = p[(size_t)(c + 0) * 128];
        float4 v1 = p[(size_t)(c + 1) * 128];
        a0.x += v0.x; a0.y += v0.y; a0.z += v0.z; a0.w += v0.w;
        a1.x += v1.x; a1.y += v1.y; a1.z += v1.z; a1.w += v1.w;
    }
    ((float4*)out)[idx4] = make_float4(a0.x + a1.x, a0.y + a1.y,
                                       a0.z + a1.z, a0.w + a1.w);
}

// ---------------------------------------------------------------------------
extern "C" void kernel_launch(void* const* d_in, const int* in_sizes, int n_in,
                              void* d_out, int out_size)
{
    const float* features = (const float*)d_in[0];
    const float* dh       = (const float*)d_in[1];
    const float* W_enc    = (const float*)d_in[2];
    const float* b_enc    = (const float*)d_in[3];
    const float* W_dec    = (const float*)d_in[4];
    const float* b_dec    = (const float*)d_in[5];
    const float* W_v      = (const float*)d_in[6];
    const float* b_v      = (const float*)d_in[7];

    float* out  = (float*)d_out;        // [B,E]
    float* attn = out + BB * EE;        // [B,L]

    cudaFuncSetAttribute(score_kernel,
                         cudaFuncAttributeMaxDynamicSharedMemorySize,
                         SMEM_BYTES);

    setup_kernel<<<64, 256>>>(W_enc, dh, W_dec, b_enc, b_dec);
    score_kernel<<<(BB * LL) / 128, 512, SMEM_BYTES>>>(features, W_v, b_v);
    wsum_attn<<<dim3(64, BB), 512>>>(attn);
    wsum_reduce<<<(BB * EE) / 512, 128>>>(out);
}

// round 14
// speedup vs baseline: 1.0838x; 1.0838x over previous
#include <cuda_runtime.h>
#include <cuda_fp16.h>
#include <cstdint>

#define BB 32
#define LL 4096
#define EE 512
#define HH 512
#define AA 256

// ---------------- scratch (__device__ globals; no allocs allowed) ----------
__device__ float g_dec[BB * AA];                 // dec_attn + b_enc + b_dec
__device__ float g_scores[BB * LL];              // pre-softmax scores
__device__ float g_bm[BB * 32];                  // per-score-block max
__device__ float g_bs[BB * 32];                  // per-score-block sum-exp
__device__ float g_partial[BB * 32 * EE];        // exp-weighted feature partials
__device__ __half g_Bh[AA * EE];                 // W_enc^T fp16, [a][k] K-major

// ---------------- family-portable PTX helpers ------------------------------
__device__ __forceinline__ uint32_t smem_u32(const void* p) {
    uint32_t a;
    asm("{ .reg .u64 t; cvta.to.shared.u64 t, %1; cvt.u32.u64 %0, t; }"
        : "=r"(a) : "l"(p));
    return a;
}
__device__ __forceinline__ uint32_t pack_h2(float lo, float hi) {
    uint32_t r;
    asm("cvt.rn.f16x2.f32 %0, %1, %2;" : "=r"(r) : "f"(hi), "f"(lo));
    return r;
}
#define LDSM4(r, addr)                                                        \
    asm volatile("ldmatrix.sync.aligned.m8n8.x4.shared.b16 {%0,%1,%2,%3}, [%4];" \
        : "=r"((r)[0]), "=r"((r)[1]), "=r"((r)[2]), "=r"((r)[3]) : "r"(addr))

#define MMA_F16(d, a, b0, b1)                                                 \
    asm volatile("mma.sync.aligned.m16n8k16.row.col.f32.f16.f16.f32 "         \
        "{%0,%1,%2,%3}, {%4,%5,%6,%7}, {%8,%9}, {%0,%1,%2,%3};"               \
        : "+f"((d)[0]), "+f"((d)[1]), "+f"((d)[2]), "+f"((d)[3])              \
        : "r"((a)[0]), "r"((a)[1]), "r"((a)[2]), "r"((a)[3]),                 \
          "r"(b0), "r"(b1))

#define CP16(dst, src)                                                        \
    asm volatile("cp.async.cg.shared.global [%0], [%1], 16;"                  \
        :: "r"(dst), "l"(src) : "memory")
#define CP_COMMIT() asm volatile("cp.async.commit_group;" ::: "memory")
#define CP_WAIT0()  asm volatile("cp.async.wait_group 0;" ::: "memory")

// ---------------- SMEM layout (bytes), PADDED addressing (SA=72) -----------
#define SA 72                 // padded k-stride (halfs) -> conflict-free ldmatrix
#define A_SLOT 18432          // 128 rows x SA halfs
#define OFF_A  0              // 8 resident A slots = 147456 B
#define OFF_B  147456         // B: 2-slot double buffer
#define B_SLOT 36864          // 256 rows x SA halfs
#define SMEM_BYTES 221184     // 216 KB
// tail scratch overlays the dead B region:
#define OFF_SDEC OFF_B              // 256 f32
#define OFF_SWV  (OFF_B + 1024)     // 256 f32
#define OFF_SRED (OFF_B + 2048)     // 512 f32 (stats reuse)
#define OFF_EW   (OFF_B + 4096)     // 128 f32 exp weights
#define OFF_PSC  (OFF_B + 8192)     // 8 x 512 f32 colsum partials

// ---------------------------------------------------------------------------
// setup: blocks [0,32) tiled transpose W_enc -> fp16 K-major (coalesced);
//        blocks [32,64) dec projection.
// ---------------------------------------------------------------------------
__global__ __launch_bounds__(256) void setup_kernel(
    const float* __restrict__ W_enc, const float* __restrict__ dh,
    const float* __restrict__ W_dec, const float* __restrict__ b_enc,
    const float* __restrict__ b_dec)
{
    if (blockIdx.x < 32) {
        __shared__ __half sh[64][65];
        const int kt = blockIdx.x >> 2;
        const int at = blockIdx.x & 3;
        const int k0 = kt * 64, a0 = at * 64;
#pragma unroll
        for (int i = 0; i < 16; i++) {
            int idx = threadIdx.x + i * 256;
            int r = idx >> 6, ca = idx & 63;
            sh[ca][r] = __float2half_rn(W_enc[(size_t)(k0 + r) * AA + a0 + ca]);
        }
        __syncthreads();
#pragma unroll
        for (int i = 0; i < 16; i++) {
            int idx = threadIdx.x + i * 256;
            int arr = idx >> 6, ck = idx & 63;
            g_Bh[(size_t)(a0 + arr) * EE + k0 + ck] = sh[arr][ck];
        }
    } else {
        int b = blockIdx.x - 32, a = threadIdx.x;
        __shared__ float shh[HH];
        for (int h = threadIdx.x; h < HH; h += 256) shh[h] = dh[b * HH + h];
        __syncthreads();
        float acc = 0.f;
#pragma unroll 8
        for (int h = 0; h < HH; h++) acc = fmaf(shh[h], W_dec[h * AA + a], acc);
        g_dec[b * AA + a] = acc + b_enc[a] + b_dec[a];
    }
}

// ---------------------------------------------------------------------------
// Fused: score GEMM (padded layout, resident A) + softmax stats + in-SMEM
// exp-weighted feature partial sum. One barrier per K-chunk.
// ---------------------------------------------------------------------------
__global__ __launch_bounds__(512, 1) void score_kernel(
    const float* __restrict__ features,
    const float* __restrict__ W_v,
    const float* __restrict__ b_v)
{
    extern __shared__ __align__(16) char smem[];
    const uint32_t sb = smem_u32(smem);

    const int tid  = threadIdx.x;
    const int lane = tid & 31;
    const int wid  = tid >> 5;
    const int warp_m = wid & 3;
    const int warp_n = wid >> 2;
    const int row0 = blockIdx.x * 128;
    const int b    = row0 >> 12;

    const int m_base = warp_m * 32;
    const int n_base = warp_n * 64;
    const uint32_t aoff =
        (uint32_t)((m_base + (lane & 15)) * SA + (lane >> 4) * 8) * 2;
    const uint32_t boff =
        (uint32_t)((n_base + (lane >> 4) * 8 + (lane & 7)) * SA +
                   ((lane >> 3) & 1) * 8) * 2;

    float d[2][8][4];
#pragma unroll
    for (int mt = 0; mt < 2; mt++)
#pragma unroll
        for (int nt = 0; nt < 8; nt++)
#pragma unroll
            for (int q = 0; q < 4; q++) d[mt][nt][q] = 0.f;

    // A loads: thread covers row tid/4, 16 floats at col (tid&3)*16
    const int ar = tid >> 2, aq = tid & 3;
    const float4* f4 = (const float4*)features +
                       ((size_t)row0 + ar) * 128 + aq * 4;
    const uint32_t a_sts = (uint32_t)(ar * SA + aq * 16) * 2;

    float4 fr[4];

    auto cp_b = [&](int chunk) {
        const uint32_t base = sb + OFF_B + (uint32_t)(chunk & 1) * B_SLOT;
        const int k0 = chunk * 64;
#pragma unroll
        for (int i = 0; i < 4; i++) {
            int idx = tid + i * 512;            // [0,2048)
            int a = idx >> 3, seg = idx & 7;
            uint32_t dst = base + (uint32_t)(a * SA + seg * 8) * 2;
            CP16(dst, g_Bh + (size_t)a * EE + k0 + seg * 8);
        }
        CP_COMMIT();
    };
    auto lda = [&](int chunk) {
#pragma unroll
        for (int j = 0; j < 4; j++) fr[j] = f4[chunk * 16 + j];
    };
    auto sts_a = [&](int chunk) {
        char* dst = smem + OFF_A + chunk * A_SLOT + a_sts;
        *(uint4*)dst = make_uint4(
            pack_h2(fr[0].x, fr[0].y), pack_h2(fr[0].z, fr[0].w),
            pack_h2(fr[1].x, fr[1].y), pack_h2(fr[1].z, fr[1].w));
        *(uint4*)(dst + 16) = make_uint4(
            pack_h2(fr[2].x, fr[2].y), pack_h2(fr[2].z, fr[2].w),
            pack_h2(fr[3].x, fr[3].y), pack_h2(fr[3].z, fr[3].w));
    };

    // prologue: B(0) in flight; A(0) staged; A(1) in regs
    cp_b(0);
    lda(0); sts_a(0);
    lda(1);

    for (int c = 0; c < 8; c++) {
        if (c < 7) sts_a(c + 1);           // resident slot c+1 (unique)
        CP_WAIT0();                        // B(c) arrived (slot c&1)
        __syncthreads();                   // visibility + compute(c-1) done
        if (c < 7) {
            cp_b(c + 1);                   // slot (c+1)&1 free (bar passed)
            if (c < 6) lda(c + 2);
        }

        const uint32_t aBase = sb + OFF_A + (uint32_t)c * A_SLOT + aoff;
        const uint32_t bBase = sb + OFF_B + (uint32_t)(c & 1) * B_SLOT;
#pragma unroll
        for (int ks = 0; ks < 4; ks++) {
            uint32_t ah[2][4];
#pragma unroll
            for (int mt = 0; mt < 2; mt++)
                LDSM4(ah[mt], aBase + (uint32_t)(mt * 16 * SA + ks * 16) * 2);
#pragma unroll
            for (int ntp = 0; ntp < 4; ntp++) {
                uint32_t bh[4];
                LDSM4(bh, bBase + boff +
                          (uint32_t)(ntp * 16 * SA + ks * 16) * 2);
#pragma unroll
                for (int mt = 0; mt < 2; mt++)
#pragma unroll
                    for (int t = 0; t < 2; t++)
                        MMA_F16(d[mt][ntp * 2 + t], ah[mt],
                                bh[2 * t], bh[2 * t + 1]);
            }
        }
    }

    // ---- B region dead: stage dec/W_v (1 ldg/thread) ------------------------
    __syncthreads();
    float* sdec = (float*)(smem + OFF_SDEC);
    float* swv  = (float*)(smem + OFF_SWV);
    float* sred = (float*)(smem + OFF_SRED);
    float* ews  = (float*)(smem + OFF_EW);
    float* psc  = (float*)(smem + OFF_PSC);
    if (tid < 256) sdec[tid] = g_dec[b * AA + tid];
    else           swv[tid - 256] = W_v[tid - 256];
    __syncthreads();

    // ---- epilogue: + dec, relu, dot W_v; quad shuffle + 4-way smem reduce --
#pragma unroll
    for (int mt = 0; mt < 2; mt++) {
        float s0 = 0.f, s1 = 0.f;
#pragma unroll
        for (int nt = 0; nt < 8; nt++) {
            int c0 = n_base + nt * 8 + (lane & 3) * 2;
            float e0 = sdec[c0], e1 = sdec[c0 + 1];
            float w0 = swv[c0], w1 = swv[c0 + 1];
            s0 = fmaf(fmaxf(d[mt][nt][0] + e0, 0.f), w0, s0);
            s0 = fmaf(fmaxf(d[mt][nt][1] + e1, 0.f), w1, s0);
            s1 = fmaf(fmaxf(d[mt][nt][2] + e0, 0.f), w0, s1);
            s1 = fmaf(fmaxf(d[mt][nt][3] + e1, 0.f), w1, s1);
        }
        s0 += __shfl_xor_sync(~0u, s0, 1);
        s0 += __shfl_xor_sync(~0u, s0, 2);
        s1 += __shfl_xor_sync(~0u, s1, 1);
        s1 += __shfl_xor_sync(~0u, s1, 2);
        if ((lane & 3) == 0) {
            int r = m_base + mt * 16 + (lane >> 2);
            sred[r * 4 + warp_n] = s0;
            sred[(r + 8) * 4 + warp_n] = s1;
        }
    }
    __syncthreads();

    float s = -1e30f;
    if (tid < 128) {
        s = sred[tid * 4] + sred[tid * 4 + 1] +
            sred[tid * 4 + 2] + sred[tid * 4 + 3] + __ldg(b_v);
        g_scores[row0 + tid] = s;
    }
    __syncthreads();

    // ---- block softmax stats + exp weights ---------------------------------
    float* st = sred;
    float m = s;
#pragma unroll
    for (int o = 16; o; o >>= 1) m = fmaxf(m, __shfl_xor_sync(~0u, m, o));
    if (lane == 0) st[wid] = m;
    __syncthreads();
    if (tid == 0) {
        float M = st[0];
#pragma unroll
        for (int i = 1; i < 16; i++) M = fmaxf(M, st[i]);
        st[16] = M;
    }
    __syncthreads();
    const float M = st[16];
    float e = (tid < 128) ? __expf(s - M) : 0.f;
    if (tid < 128) ews[tid] = e;
#pragma unroll
    for (int o = 16; o; o >>= 1) e += __shfl_xor_sync(~0u, e, o);
    __syncthreads();
    if (lane == 0) st[wid] = e;
    __syncthreads();
    if (tid == 0) {
        float S = 0.f;
#pragma unroll
        for (int i = 0; i < 16; i++) S += st[i];
        g_bm[blockIdx.x] = M;
        g_bs[blockIdx.x] = S;
    }
    __syncthreads();                       // ews visible

    // ---- vectorized in-SMEM weighted sum (padded layout) --------------------
    // P[e] = sum_l ews[l] * A16[l][e];  thread = (granule col, row octile)
    {
        const int gcol = tid & 63;         // 8 chunks x 8 granules
        const int sub  = tid >> 6;         // row octile 0..7
        const int ch   = gcol >> 3, gq = gcol & 7;
        char* abase = smem + OFF_A + ch * A_SLOT + gq * 16;
        float acc[8];
#pragma unroll
        for (int j = 0; j < 8; j++) acc[j] = 0.f;
#pragma unroll
        for (int i = 0; i < 16; i++) {
            int l = sub * 16 + i;
            uint4 v = *(uint4*)(abase + l * (SA * 2));
            float w = ews[l];
            float2 p;
            p = __half22float2(*(__half2*)&v.x);
            acc[0] = fmaf(p.x, w, acc[0]); acc[1] = fmaf(p.y, w, acc[1]);
            p = __half22float2(*(__half2*)&v.y);
            acc[2] = fmaf(p.x, w, acc[2]); acc[3] = fmaf(p.y, w, acc[3]);
            p = __half22float2(*(__half2*)&v.z);
            acc[4] = fmaf(p.x, w, acc[4]); acc[5] = fmaf(p.y, w, acc[5]);
            p = __half22float2(*(__half2*)&v.w);
            acc[6] = fmaf(p.x, w, acc[6]); acc[7] = fmaf(p.y, w, acc[7]);
        }
#pragma unroll
        for (int j = 0; j < 8; j++)
            psc[sub * 512 + gcol * 8 + j] = acc[j];
    }
    __syncthreads();
    {
        float sum = 0.f;
#pragma unroll
        for (int sbi = 0; sbi < 8; sbi++)
            sum += psc[sbi * 512 + tid];
        g_partial[(size_t)blockIdx.x * EE + tid] = sum;
    }
}

// ---------------------------------------------------------------------------
// finalize: blocks [0,32) -> output[b,:] from 32 rescaled partials;
//           blocks [32,160) -> attn weights (1024 l's per block).
// ---------------------------------------------------------------------------
__global__ __launch_bounds__(512) void finalize_kernel(
    float* __restrict__ out, float* __restrict__ attn)
{
    const int bx = blockIdx.x;
    const int tid = threadIdx.x;
    const int b = (bx < 32) ? bx : ((bx - 32) >> 2);
    __shared__ float scale[32];
    __shared__ float MS[2];

    if (tid < 32) {
        float m = g_bm[b * 32 + tid];
        float sl = g_bs[b * 32 + tid];
        float M = m;
#pragma unroll
        for (int o = 16; o; o >>= 1) M = fmaxf(M, __shfl_xor_sync(~0u, M, o));
        float S = sl * __expf(m - M);
#pragma unroll
        for (int o = 16; o; o >>= 1) S += __shfl_xor_sync(~0u, S, o);
        if (tid == 0) { MS[0] = M; MS[1] = S; }
    }
    __syncthreads();
    const float M = MS[0];
    const float invS = 1.f / MS[1];

    if (bx < 32) {
        if (tid < 32) scale[tid] = __expf(g_bm[b * 32 + tid] - M) * invS;
        __syncthreads();
        float acc = 0.f;
#pragma unroll
        for (int blk = 0; blk < 32; blk++)
            acc = fmaf(g_partial[(size_t)(b * 32 + blk) * EE + tid],
                       scale[blk], acc);
        out[b * EE + tid] = acc;
    } else {
        const int chunk = (bx - 32) & 3;
        const float* sc = g_scores + (size_t)b * LL + chunk * 1024;
        float* w = attn + (size_t)b * LL + chunk * 1024;
#pragma unroll
        for (int i = 0; i < 2; i++)
            w[tid + i * 512] = __expf(sc[tid + i * 512] - M) * invS;
    }
}

// ---------------------------------------------------------------------------
extern "C" void kernel_launch(void* const* d_in, const int* in_sizes, int n_in,
                              void* d_out, int out_size)
{
    const float* features = (const float*)d_in[0];
    const float* dh       = (const float*)d_in[1];
    const float* W_enc    = (const float*)d_in[2];
    const float* b_enc    = (const float*)d_in[3];
    const float* W_dec    = (const float*)d_in[4];
    const float* b_dec    = (const float*)d_in[5];
    const float* W_v      = (const float*)d_in[6];
    const float* b_v      = (const float*)d_in[7];

    float* out  = (float*)d_out;        // [B,E]
    float* attn = out + BB * EE;        // [B,L]

    cudaFuncSetAttribute(score_kernel,
                         cudaFuncAttributeMaxDynamicSharedMemorySize,
                         SMEM_BYTES);

    setup_kernel<<<64, 256>>>(W_enc, dh, W_dec, b_enc, b_dec);
    score_kernel<<<(BB * LL) / 128, 512, SMEM_BYTES>>>(features, W_v, b_v);
    finalize_kernel<<<160, 512>>>(out, attn);
}